// round 15
// baseline (speedup 1.0000x reference)
#include <cuda_runtime.h>
#include <cuda_bf16.h>
#include <math.h>

#define HWSZ   19200
#define IMW    160
#define NPIX   2400
#define NBLKC  19          // 19 x 1024 cells = 19456 >= 19200
#define NCOBJ  7           // object classes 1..7
#define NPT    10          // pixels per thread in prep (10*256 >= 2400)
#define NTHR   256

typedef unsigned long long ull;

// ---------------- packed f32x2 helpers ----------------
__device__ __forceinline__ ull pk2(float lo, float hi) {
    ull r; asm("mov.b64 %0, {%1, %2};" : "=l"(r) : "f"(lo), "f"(hi)); return r;
}
__device__ __forceinline__ void up2(ull v, float& lo, float& hi) {
    asm("mov.b64 {%0, %1}, %2;" : "=f"(lo), "=f"(hi) : "l"(v));
}
__device__ __forceinline__ ull add2(ull a, ull b) {
    ull r; asm("add.rn.f32x2 %0, %1, %2;" : "=l"(r) : "l"(a), "l"(b)); return r;
}
__device__ __forceinline__ ull mul2(ull a, ull b) {
    ull r; asm("mul.rn.f32x2 %0, %1, %2;" : "=l"(r) : "l"(a), "l"(b)); return r;
}
__device__ __forceinline__ ull fma2(ull a, ull b, ull c) {
    ull r; asm("fma.rn.f32x2 %0, %1, %2, %3;" : "=l"(r) : "l"(a), "l"(b), "l"(c)); return r;
}

// ---------------- global scratch (tiny: partials + counters only) ----------------
__device__ float g_pv[NCOBJ * NBLKC];
__device__ int   g_pl[NCOBJ * NBLKC];
__device__ float g_pds[NCOBJ * NBLKC];
__device__ int   g_cnt[NCOBJ];
__device__ unsigned g_ctr = 0;                   // arrival counter (self-resetting)

struct P4 { ull a, b; };

// ============================================================================
// Single fused kernel: per-block prep (own class) -> vote (4 cells/thread) ->
// partials; last-arriving block does the final per-class reduction + outputs.
// Grid (19, 7), 256 threads.
// ============================================================================
__global__ void __launch_bounds__(256) hough_kernel(const int* __restrict__ labels,
                                                    const int* __restrict__ masks,
                                                    const float* __restrict__ vp,
                                                    const float* __restrict__ extents,
                                                    const float* __restrict__ poses,
                                                    const float* __restrict__ meta,
                                                    float* __restrict__ out)
{
    // pair p: s_xy[p] = (-xs pair, -ys pair); s_nn[p] = (nx' pair, ny' pair)
    __shared__ __align__(16) P4     s_xy[1200];   // 19200 B
    __shared__ __align__(16) P4     s_nn[1200];   // 19200 B
    __shared__ __align__(16) float2 s_dp[1200];   //  9600 B
    __shared__ int s_cnt[NPT][8];
    __shared__ int s_base[NPT][8];
    __shared__ int s_npix;
    __shared__ float s_wv[8];
    __shared__ int   s_wl[8];
    __shared__ float s_wd[8];
    __shared__ unsigned s_old;

    const int cls  = blockIdx.y;            // 0..6 (class cls+1)
    const int bx   = blockIdx.x;            // 0..18
    const int tid  = threadIdx.x;           // 0..255
    const int lane = tid & 31, warp = tid >> 5;   // 8 warps
    const int myc  = cls + 1;
    const unsigned below = (1u << lane) - 1u;

    // ================== PREP (this block's class only) ==================
    int cv[NPT];
    {
        int labv[NPT], mskv[NPT];
        #pragma unroll
        for (int k = 0; k < NPT; k++) {
            int i = k * NTHR + tid;
            labv[k] = (i < NPIX) ? labels[i * 8] : 0;
        }
        #pragma unroll
        for (int k = 0; k < NPT; k++) {
            int i = k * NTHR + tid;
            mskv[k] = (i < NPIX) ? masks[i * 8] : 0;
        }
        #pragma unroll
        for (int k = 0; k < NPT; k++)
            cv[k] = (mskv[k] > 0 && labv[k] > 0) ? labv[k] : 0;
    }

    // count pass
    #pragma unroll
    for (int k = 0; k < NPT; k++) {
        const unsigned bal = __ballot_sync(0xFFFFFFFFu, cv[k] == myc);
        if (lane == 0) s_cnt[k][warp] = __popc(bal);
    }
    __syncthreads();

    // serial exclusive prefix in (k, warp) order == ascending pixel index
    if (tid == 0) {
        int run = 0;
        #pragma unroll
        for (int k = 0; k < NPT; k++)
            for (int w = 0; w < 8; w++) {
                const int t = s_cnt[k][w];
                s_base[k][w] = run;
                run += t;
            }
        s_npix = run;
    }
    __syncthreads();

    const int npix  = s_npix;
    const int pad   = (npix + 7) & ~7;
    const int npair = pad >> 1;

    // placement pass
    float* sxyf = (float*)s_xy;
    float* snnf = (float*)s_nn;
    float* sdpf = (float*)s_dp;
    #pragma unroll
    for (int k = 0; k < NPT; k++) {
        const bool m = (cv[k] == myc);
        const unsigned bal = __ballot_sync(0xFFFFFFFFu, m);
        if (m) {
            const int i = k * NTHR + tid;
            const int idx = i * 8;
            const float vx = vp[(myc * 3 + 0) * HWSZ + idx];
            const float vy = vp[(myc * 3 + 1) * HWSZ + idx];
            const float vz = vp[(myc * 3 + 2) * HWSZ + idx];
            const float nrm = sqrtf(vx * vx + vy * vy) + 1e-6f;
            const float nxp = (vx / nrm) * (1.0f / 0.9f);
            const float nyp = (vy / nrm) * (1.0f / 0.9f);
            const float xs = (float)(idx % IMW);
            const float ys = (float)(idx / IMW);
            const int slot = s_base[k][warp] + __popc(bal & below);
            const int p = slot >> 1, h = slot & 1;
            sxyf[p * 4 + h]     = -xs;
            sxyf[p * 4 + 2 + h] = -ys;
            snnf[p * 4 + h]     = nxp;
            snnf[p * 4 + 2 + h] = nyp;
            sdpf[p * 2 + h]     = expf(vz);
        }
    }
    for (int s = npix + tid; s < pad; s += NTHR) {
        const int p = s >> 1, h = s & 1;
        sxyf[p * 4 + h] = 0.f;  sxyf[p * 4 + 2 + h] = 0.f;
        snnf[p * 4 + h] = 0.f;  snnf[p * 4 + 2 + h] = 0.f;
        sdpf[p * 2 + h] = 0.f;
    }
    if (tid == 0 && bx == 0) g_cnt[cls] = npix;
    __syncthreads();

    // ================== VOTE: 4 cells per thread ==================
    int  locs[4];
    ull  gx2[4], gy2[4];
    bool valid[4];
    #pragma unroll
    for (int c4 = 0; c4 < 4; c4++) {
        const int loc = bx * 1024 + c4 * NTHR + tid;
        locs[c4]  = loc;
        valid[c4] = (loc < HWSZ);
        const float gx = (float)(loc % IMW);
        const float gy = (float)(loc / IMW);
        gx2[c4] = pk2(gx, gx);
        gy2[c4] = pk2(gy, gy);
    }

    float v[4]  = {0.f, 0.f, 0.f, 0.f};
    float ds[4] = {0.f, 0.f, 0.f, 0.f};

    #pragma unroll 2
    for (int p = 0; p < npair; p++) {
        const P4 axy = s_xy[p];
        const P4 ann = s_nn[p];
        const float2 dd = s_dp[p];
        #pragma unroll
        for (int c4 = 0; c4 < 4; c4++) {
            ull dx2  = add2(gx2[c4], axy.a);
            ull dy2  = add2(gy2[c4], axy.b);
            ull dot2 = fma2(dy2, ann.b, mul2(dx2, ann.a));   // dot' = dot/0.9
            ull d22  = fma2(dy2, dy2, mul2(dx2, dx2));       // d2
            ull q2   = mul2(dot2, dot2);
            float dot0, dot1, q0, q1, e0, e1;
            up2(dot2, dot0, dot1); up2(q2, q0, q1); up2(d22, e0, e1);
            if (dot0 > 0.f && q0 > e0) { v[c4] += 1.f; ds[c4] += dd.x; }
            if (dot1 > 0.f && q1 > e1) { v[c4] += 1.f; ds[c4] += dd.y; }
        }
    }
    #pragma unroll
    for (int c4 = 0; c4 < 4; c4++)
        if (!valid[c4]) v[c4] = -1.f;        // sentinel: never wins argmax

    // fold 4 cells (ascending loc order; strict > keeps lowest loc on ties)
    float bv = v[0], bd = ds[0]; int bl = locs[0];
    #pragma unroll
    for (int c4 = 1; c4 < 4; c4++)
        if (v[c4] > bv) { bv = v[c4]; bl = locs[c4]; bd = ds[c4]; }

    // warp shuffle argmax (desc v, asc loc on tie)
    #pragma unroll
    for (int off = 16; off > 0; off >>= 1) {
        float ov = __shfl_down_sync(0xFFFFFFFFu, bv, off);
        int   ol = __shfl_down_sync(0xFFFFFFFFu, bl, off);
        float od = __shfl_down_sync(0xFFFFFFFFu, bd, off);
        if (ov > bv || (ov == bv && ol < bl)) { bv = ov; bl = ol; bd = od; }
    }
    if (lane == 0) { s_wv[warp] = bv; s_wl[warp] = bl; s_wd[warp] = bd; }
    __syncthreads();

    if (warp == 0) {
        float wv = (lane < 8) ? s_wv[lane] : -1.f;
        int   wl = (lane < 8) ? s_wl[lane] : 0x7FFFFFFF;
        float wd = (lane < 8) ? s_wd[lane] : 0.f;
        #pragma unroll
        for (int off = 4; off > 0; off >>= 1) {
            float ov = __shfl_down_sync(0xFFFFFFFFu, wv, off);
            int   ol = __shfl_down_sync(0xFFFFFFFFu, wl, off);
            float od = __shfl_down_sync(0xFFFFFFFFu, wd, off);
            if (ov > wv || (ov == wv && ol < wl)) { wv = ov; wl = ol; wd = od; }
        }
        if (lane == 0) {
            g_pv [cls * NBLKC + bx] = wv;
            g_pl [cls * NBLKC + bx] = wl;
            g_pds[cls * NBLKC + bx] = wd;
        }
    }

    // ---- arrival: last block performs final reduction + outputs ----
    __threadfence();
    __syncthreads();
    if (tid == 0) s_old = atomicAdd(&g_ctr, 1u);
    __syncthreads();
    if (s_old != (unsigned)(NBLKC * NCOBJ) - 1u) return;
    __threadfence();

    // warp c handles class c (0..7); class 0 never votes -> zeros path
    const int c = warp;
    {
        float vmax = 0.f, dsum = 0.f, nv = 0.f;
        int best = 0;
        if (c > 0) {
            const int ci = c - 1;
            float bc = -1.f, bd2 = 0.f; int bl2 = 0x7FFFFFFF;
            if (lane < NBLKC) {
                bc  = g_pv [ci * NBLKC + lane];
                bl2 = g_pl [ci * NBLKC + lane];
                bd2 = g_pds[ci * NBLKC + lane];
            }
            #pragma unroll
            for (int off = 16; off > 0; off >>= 1) {
                float ov = __shfl_down_sync(0xFFFFFFFFu, bc, off);
                int   ol = __shfl_down_sync(0xFFFFFFFFu, bl2, off);
                float od = __shfl_down_sync(0xFFFFFFFFu, bd2, off);
                if (ov > bc || (ov == bc && ol < bl2)) { bc = ov; bl2 = ol; bd2 = od; }
            }
            vmax = bc; best = bl2; dsum = bd2;
            nv = (float)g_cnt[ci];
        }

        if (lane == 0) {
            const float dbar = dsum / fmaxf(vmax, 1.f);
            const float cx = (float)(best % IMW);
            const float cy = (float)(best / IMW);
            const float fx = meta[0], px = meta[2], fy = meta[4], py = meta[5];
            const float e0 = extents[c * 3 + 0];
            const float e1 = extents[c * 3 + 1];
            const float e2 = extents[c * 3 + 2];
            const float diag = sqrtf(e0 * e0 + e1 * e1 + e2 * e2);
            const float safe = fmaxf(dbar, 1e-6f);
            const float bw = diag * fx / safe;
            const float bh = diag * fy / safe;
            const float score = vmax / fmaxf(nv, 1.f);

            float* box = out + c * 7;
            box[0] = 0.f;
            box[1] = (float)c;
            box[2] = cx - bw * 0.5f;
            box[3] = cy - bh * 0.5f;
            box[4] = cx + bw * 0.5f;
            box[5] = cy + bh * 0.5f;
            box[6] = score;

            float* pp = out + 56 + c * 7;
            pp[0] = poses[c * 7 + 0];
            pp[1] = poses[c * 7 + 1];
            pp[2] = poses[c * 7 + 2];
            pp[3] = poses[c * 7 + 3];
            pp[4] = (cx - px) * dbar / fmaxf(fx, 1e-6f);
            pp[5] = (cy - py) * dbar / fmaxf(fy, 1e-6f);
            pp[6] = dbar;
        }
    }
    if (tid == 0) g_ctr = 0;                  // reset for next replay
}

// ============================================================================
extern "C" void kernel_launch(void* const* d_in, const int* in_sizes, int n_in,
                              void* d_out, int out_size)
{
    const int*   labels  = (const int*)d_in[0];
    const int*   masks   = (const int*)d_in[1];
    const float* vp      = (const float*)d_in[2];
    const float* extents = (const float*)d_in[3];
    const float* poses   = (const float*)d_in[4];
    const float* meta    = (const float*)d_in[5];
    float* out = (float*)d_out;

    hough_kernel<<<dim3(NBLKC, NCOBJ), 256>>>(labels, masks, vp, extents, poses, meta, out);
}